// round 5
// baseline (speedup 1.0000x reference)
#include <cuda_runtime.h>
#include <cuda_bf16.h>
#include <math.h>

#define LREF 384
#define DPC 128
#define HN 4
#define DHD 32
#define KTOT (LREF*DHD)   // 12288

typedef __nv_bfloat16 bf16;
typedef __nv_bfloat162 bf162;

// ---------------- scratch (device globals) ----------------------------------
__device__ unsigned char g_q8[(size_t)HN*LREF*KTOT]; // [h][i][n*32+d] e4m3, unscaled
__device__ unsigned char g_k8[(size_t)HN*LREF*KTOT]; // [h][j][n*32+d] e4m3, unscaled
__device__ bf16 g_vb[(size_t)HN*LREF*KTOT];     // [h][j][n*32+d]
__device__ bf16 g_gateb[(size_t)LREF*LREF*DPC]; // [row=n*L+i][c]
__device__ bf16 g_omb[(size_t)LREF*LREF*DPC];   // [row=n*L+i][h*32+d]
__device__ float g_attn[(size_t)HN*LREF*LREF];  // fp32 logits (bias-init + atomics)
__device__ bf16 g_attnb[(size_t)HN*LREF*LREF];  // softmaxed, bf16

// ---------------- ptx helpers ------------------------------------------------
__device__ __forceinline__ void ldsm4(unsigned &r0,unsigned &r1,unsigned &r2,unsigned &r3,unsigned a){
    asm volatile("ldmatrix.sync.aligned.m8n8.x4.shared.b16 {%0,%1,%2,%3},[%4];"
        :"=r"(r0),"=r"(r1),"=r"(r2),"=r"(r3):"r"(a));
}
__device__ __forceinline__ void ldsm4t(unsigned &r0,unsigned &r1,unsigned &r2,unsigned &r3,unsigned a){
    asm volatile("ldmatrix.sync.aligned.m8n8.x4.trans.shared.b16 {%0,%1,%2,%3},[%4];"
        :"=r"(r0),"=r"(r1),"=r"(r2),"=r"(r3):"r"(a));
}
__device__ __forceinline__ void mma_bf16(float c[4], const unsigned a[4], const unsigned b[2]){
    asm volatile("mma.sync.aligned.m16n8k16.row.col.f32.bf16.bf16.f32 "
        "{%0,%1,%2,%3},{%4,%5,%6,%7},{%8,%9},{%0,%1,%2,%3};"
        :"+f"(c[0]),"+f"(c[1]),"+f"(c[2]),"+f"(c[3])
        :"r"(a[0]),"r"(a[1]),"r"(a[2]),"r"(a[3]),"r"(b[0]),"r"(b[1]));
}
__device__ __forceinline__ void mma_fp8(float c[4], const unsigned a[4], const unsigned b[2]){
    asm volatile("mma.sync.aligned.m16n8k32.row.col.f32.e4m3.e4m3.f32 "
        "{%0,%1,%2,%3},{%4,%5,%6,%7},{%8,%9},{%0,%1,%2,%3};"
        :"+f"(c[0]),"+f"(c[1]),"+f"(c[2]),"+f"(c[3])
        :"r"(a[0]),"r"(a[1]),"r"(a[2]),"r"(a[3]),"r"(b[0]),"r"(b[1]));
}
__device__ __forceinline__ void cpa16(unsigned saddr, const void* g) {
    asm volatile("cp.async.cg.shared.global [%0],[%1],16;\n" :: "r"(saddr), "l"(g));
}
__device__ __forceinline__ void cpa_commit() { asm volatile("cp.async.commit_group;\n"); }
template<int N>
__device__ __forceinline__ void cpa_wait() { asm volatile("cp.async.wait_group %0;\n" :: "n"(N)); }

__device__ __forceinline__ unsigned pk2(float a, float b){
    bf162 t = __floats2bfloat162_rn(a, b);
    return *(unsigned*)&t;
}
__device__ __forceinline__ unsigned short pk8(float lo, float hi){
    unsigned short u;
    asm("cvt.rn.satfinite.e4m3x2.f32 %0, %2, %1;" : "=h"(u) : "f"(lo), "f"(hi));
    return u;
}

// warp k16-step (bf16): A rows 128B [m][k64], B rows 128B [n][k64], SW128-swizzled
template<int MT,int NT>
__device__ __forceinline__ void wstep(float (&acc)[MT][NT][4], unsigned sA, unsigned sB,
                                      int m0, int n0, int k0, int lane)
{
    unsigned a[MT][4];
    int arow = lane & 15, acg = (k0>>3) + (lane>>4);
#pragma unroll
    for (int mt = 0; mt < MT; mt++) {
        int r = m0 + mt*16 + arow;
        ldsm4(a[mt][0],a[mt][1],a[mt][2],a[mt][3], sA + r*128 + ((acg ^ (r&7))<<4));
    }
    int brow_off = (lane & 7) + ((lane>>4)<<3);
    int bcg = (k0>>3) + ((lane>>3)&1);
#pragma unroll
    for (int nt = 0; nt < NT; nt += 2) {
        int r = n0 + nt*8 + brow_off;
        unsigned b[4];
        ldsm4(b[0],b[1],b[2],b[3], sB + r*128 + ((bcg ^ (r&7))<<4));
#pragma unroll
        for (int mt = 0; mt < MT; mt++) {
            mma_bf16(acc[mt][nt],   a[mt], b);
            mma_bf16(acc[mt][nt+1], a[mt], b+2);
        }
    }
}

// warp k32-step (fp8): A rows 128B [m][k128 bytes], B rows 128B [n][k128 bytes].
// kb = byte offset of this k-step within the 128B row (0,32,64,96).
template<int MT,int NT>
__device__ __forceinline__ void wstep8(float (&acc)[MT][NT][4], unsigned sA, unsigned sB,
                                       int m0, int n0, int kb, int lane)
{
    unsigned a[MT][4];
    int arow = lane & 15, acg = (kb>>4) + (lane>>4);
#pragma unroll
    for (int mt = 0; mt < MT; mt++) {
        int r = m0 + mt*16 + arow;
        ldsm4(a[mt][0],a[mt][1],a[mt][2],a[mt][3], sA + r*128 + ((acg ^ (r&7))<<4));
    }
    int brow_off = (lane & 7) + ((lane>>4)<<3);
    int bcg = (kb>>4) + ((lane>>3)&1);
#pragma unroll
    for (int nt = 0; nt < NT; nt += 2) {
        int r = n0 + nt*8 + brow_off;
        unsigned b[4];
        ldsm4(b[0],b[1],b[2],b[3], sB + r*128 + ((bcg ^ (r&7))<<4));
#pragma unroll
        for (int mt = 0; mt < MT; mt++) {
            mma_fp8(acc[mt][nt],   a[mt], b);
            mma_fp8(acc[mt][nt+1], a[mt], b+2);
        }
    }
}

// warp k16-step with transposed B: B buffer 256B rows [k64][n128]
template<int MT,int NT>
__device__ __forceinline__ void wstep_t(float (&acc)[MT][NT][4], unsigned sA, unsigned sB,
                                        int m0, int n0, int k0, int lane)
{
    unsigned a[MT][4];
    int arow = lane & 15, acg = (k0>>3) + (lane>>4);
#pragma unroll
    for (int mt = 0; mt < MT; mt++) {
        int r = m0 + mt*16 + arow;
        ldsm4(a[mt][0],a[mt][1],a[mt][2],a[mt][3], sA + r*128 + ((acg ^ (r&7))<<4));
    }
    int brow = k0 + (lane & 7) + (((lane>>3)&1)<<3);
    int bcg_off = lane >> 4;
#pragma unroll
    for (int nt = 0; nt < NT; nt += 2) {
        int cg = ((n0 + nt*8) >> 3) + bcg_off;
        unsigned b[4];
        ldsm4t(b[0],b[1],b[2],b[3], sB + brow*256 + ((cg ^ (brow&7))<<4));
#pragma unroll
        for (int mt = 0; mt < MT; mt++) {
            mma_bf16(acc[mt][nt],   a[mt], b);
            mma_bf16(acc[mt][nt+1], a[mt], b+2);
        }
    }
}

// -------- kernel A: LN(pair rows) + q/k/v/gate projections -------------------
// 256 threads = 8 warps (4m x 2n, each 64x64). M-tile 256 rows, N=128, K=128.
__global__ void __launch_bounds__(256) proj_kernel(
    const float* __restrict__ pair, const float* __restrict__ lng, const float* __restrict__ lnb,
    const float* __restrict__ Wq, const float* __restrict__ Wk, const float* __restrict__ Wv,
    const float* __restrict__ Wg, const float* __restrict__ bg)
{
    extern __shared__ unsigned char sm[];
    unsigned sXa = (unsigned)__cvta_generic_to_shared(sm);
    unsigned sWa = sXa + 65536;
    int tid = threadIdx.x, lane = tid & 31, warp = tid >> 5;
    int wm = warp >> 1, wn = warp & 1;
    int row0 = blockIdx.x * 256;

    // ---- LayerNorm: one thread per row; rows are p[n,i] = pair[i,n] ----
    {
        int r = tid;
        int row = row0 + r;
        int n = row / LREF, i = row - n*LREF;
        const float* x = pair + ((size_t)i*LREF + n) * DPC;
        float s = 0.f, s2 = 0.f;
#pragma unroll 8
        for (int c = 0; c < DPC; c += 4) {
            float4 t = *(const float4*)(x + c);
            s  += t.x + t.y + t.z + t.w;
            s2 += t.x*t.x + t.y*t.y + t.z*t.z + t.w*t.w;
        }
        float mean = s * (1.f/DPC);
        float rstd = rsqrtf(s2 * (1.f/DPC) - mean*mean + 1e-5f);
#pragma unroll
        for (int g = 0; g < 16; g++) {
            float4 t0 = *(const float4*)(x + g*8);
            float4 t1 = *(const float4*)(x + g*8 + 4);
            float4 w0 = *(const float4*)(lng + g*8);
            float4 w1 = *(const float4*)(lng + g*8 + 4);
            float4 b0 = *(const float4*)(lnb + g*8);
            float4 b1 = *(const float4*)(lnb + g*8 + 4);
            uint4 o;
            o.x = pk2((t0.x-mean)*rstd*w0.x + b0.x, (t0.y-mean)*rstd*w0.y + b0.y);
            o.y = pk2((t0.z-mean)*rstd*w0.z + b0.z, (t0.w-mean)*rstd*w0.w + b0.w);
            o.z = pk2((t1.x-mean)*rstd*w1.x + b1.x, (t1.y-mean)*rstd*w1.y + b1.y);
            o.w = pk2((t1.z-mean)*rstd*w1.z + b1.z, (t1.w-mean)*rstd*w1.w + b1.w);
            int kc = g >> 3, gg = g & 7;
            *(uint4*)(sm + kc*32768 + r*128 + ((gg ^ (r&7))<<4)) = o;
        }
    }
    __syncthreads();

    const float* Ws[4] = { Wq, Wk, Wv, Wg };
    for (int mat = 0; mat < 4; mat++) {
        float acc[4][8][4];
#pragma unroll
        for (int a = 0; a < 4; a++)
#pragma unroll
            for (int b = 0; b < 8; b++)
#pragma unroll
                for (int cc = 0; cc < 4; cc++) acc[a][b][cc] = 0.f;

        const float* W = Ws[mat];
        for (int kc = 0; kc < 2; kc++) {
            __syncthreads();
            for (int c = tid; c < 1024; c += 256) {
                int r = c >> 3, g = c & 7;
                const float* src = W + (size_t)r*DPC + kc*64 + g*8;
                float4 t0 = *(const float4*)src;
                float4 t1 = *(const float4*)(src + 4);
                uint4 o;
                o.x = pk2(t0.x, t0.y); o.y = pk2(t0.z, t0.w);
                o.z = pk2(t1.x, t1.y); o.w = pk2(t1.z, t1.w);
                *(uint4*)(sm + 65536 + r*128 + ((g ^ (r&7))<<4)) = o;
            }
            __syncthreads();
#pragma unroll
            for (int kk = 0; kk < 4; kk++)
                wstep<4,8>(acc, sXa + kc*32768, sWa, wm*64, wn*64, kk*16, lane);
        }

#pragma unroll
        for (int mt = 0; mt < 4; mt++)
#pragma unroll
            for (int nt = 0; nt < 8; nt++) {
                float* ac = acc[mt][nt];
                int rl = wm*64 + mt*16 + (lane >> 2);
                int c  = wn*64 + nt*8 + 2*(lane & 3);
                int h = c >> 5, d = c & 31;
#pragma unroll
                for (int half = 0; half < 2; half++) {
                    int row = row0 + rl + half*8;
                    float v0 = ac[half*2+0], v1 = ac[half*2+1];
                    int n = row / LREF, i = row - n*LREF;
                    size_t qidx = ((size_t)(h*LREF + i))*KTOT + n*DHD + d;
                    if (mat == 0) {            // q: raw (scale applied in score epilogue)
                        *(unsigned short*)&g_q8[qidx] = pk8(v0, v1);
                    } else if (mat == 1) {     // k: raw
                        *(unsigned short*)&g_k8[qidx] = pk8(v0, v1);
                    } else if (mat == 2) {
                        *(bf162*)&g_vb[qidx] = __floats2bfloat162_rn(v0, v1);
                    } else {
                        float z0 = v0 + bg[c], z1 = v1 + bg[c+1];
                        *(bf162*)&g_gateb[(size_t)row*DPC + c] =
                            __floats2bfloat162_rn(1.f/(1.f+expf(-z0)), 1.f/(1.f+expf(-z1)));
                    }
                }
            }
    }
}

// -------- kernel B: LN(bias rows) @ Wb^T -> init fp32 attn -------------------
__global__ void __launch_bounds__(128) bias_kernel(
    const float* __restrict__ bias, const float* __restrict__ lng, const float* __restrict__ lnb,
    const float* __restrict__ Wb)
{
    __shared__ float sx[16][DPC];
    int tid = threadIdx.x, warp = tid >> 5, lane = tid & 31;
    int row0 = blockIdx.x * 16;                 // row = i*L + j

    for (int rr = 0; rr < 4; rr++) {
        int r = warp * 4 + rr;
        int row = row0 + r;
        int i = row / LREF, j = row % LREF;
        const float* x = bias + ((size_t)j * LREF + i) * DPC;
        float v0 = x[lane], v1 = x[lane+32], v2 = x[lane+64], v3 = x[lane+96];
        float s = v0 + v1 + v2 + v3;
#pragma unroll
        for (int o = 16; o; o >>= 1) s += __shfl_xor_sync(0xffffffffu, s, o);
        float mean = s * (1.f / DPC);
        float d0 = v0-mean, d1 = v1-mean, d2 = v2-mean, d3 = v3-mean;
        float ss = d0*d0 + d1*d1 + d2*d2 + d3*d3;
#pragma unroll
        for (int o = 16; o; o >>= 1) ss += __shfl_xor_sync(0xffffffffu, ss, o);
        float rstd = rsqrtf(ss * (1.f / DPC) + 1e-5f);
        sx[r][lane]    = d0 * rstd * lng[lane]    + lnb[lane];
        sx[r][lane+32] = d1 * rstd * lng[lane+32] + lnb[lane+32];
        sx[r][lane+64] = d2 * rstd * lng[lane+64] + lnb[lane+64];
        sx[r][lane+96] = d3 * rstd * lng[lane+96] + lnb[lane+96];
    }
    __syncthreads();

    if (tid < 64) {
        int r = tid >> 2, h = tid & 3;
        int row = row0 + r;
        int i = row / LREF, j = row % LREF;
        const float* wrow = Wb + h * DPC;
        float acc = 0.f;
#pragma unroll
        for (int c = 0; c < DPC; c += 4) {
            float4 xv = *(const float4*)(&sx[r][c]);
            float4 wv = *(const float4*)(wrow + c);
            acc += xv.x*wv.x + xv.y*wv.y + xv.z*wv.z + xv.w*wv.w;
        }
        g_attn[((size_t)h * LREF + i) * LREF + j] = acc;
    }
}

// -------- kernel C: attn += scale*(q8.k8)  (128x128 tiles, split-K 8, fp8) ---
__global__ void __launch_bounds__(256) score_kernel()
{
    extern __shared__ unsigned char sm[];
    unsigned sA = (unsigned)__cvta_generic_to_shared(sm);     // 2 x 16KB
    unsigned sB = sA + 32768;                                 // 2 x 16KB
    int tid = threadIdx.x, lane = tid & 31, warp = tid >> 5;
    int wm = warp & 3, wn = warp >> 2;
    int h = blockIdx.z >> 3, ks = blockIdx.z & 7;
    int i0 = blockIdx.x * 128, j0 = blockIdx.y * 128;

    const unsigned char* ga = g_q8 + ((size_t)(h*LREF + i0))*KTOT + ks*(KTOT/8);
    const unsigned char* gb = g_k8 + ((size_t)(h*LREF + j0))*KTOT + ks*(KTOT/8);

    float acc[2][8][4];
#pragma unroll
    for (int a = 0; a < 2; a++)
#pragma unroll
        for (int b = 0; b < 8; b++)
#pragma unroll
            for (int cc = 0; cc < 4; cc++) acc[a][b][cc] = 0.f;

    const int NIT = (KTOT/8)/128;   // 12 iterations of k=128 bytes
    auto stage = [&](int it) {
        unsigned off = (it & 1) * 16384;
        for (int c = tid; c < 1024; c += 256) {
            int r = c >> 2, g = c & 3;            // 128 rows x 4 x 32B? no: 8 groups of 16B
            (void)r; (void)g;
        }
        // 128 rows x 128B = 1024 x 16B chunks per matrix
        for (int c = tid; c < 1024; c += 256) {
            int r = c >> 3, g = c & 7;
            unsigned d = r*128 + ((g ^ (r&7))<<4);
            cpa16(sA + off + d, ga + (size_t)r*KTOT + it*128 + g*16);
            cpa16(sB + off + d, gb + (size_t)r*KTOT + it*128 + g*16);
        }
        cpa_commit();
    };
    stage(0);
    for (int it = 0; it < NIT; it++) {
        if (it + 1 < NIT) { stage(it + 1); cpa_wait<1>(); }
        else cpa_wait<0>();
        __syncthreads();
        unsigned off = (it & 1) * 16384;
#pragma unroll
        for (int kk = 0; kk < 4; kk++)
            wstep8<2,8>(acc, sA + off, sB + off, wm*32, wn*64, kk*32, lane);
        __syncthreads();
    }

    const float SC = 0.17677669529663687f / 384.0f;
#pragma unroll
    for (int mt = 0; mt < 2; mt++)
#pragma unroll
        for (int nt = 0; nt < 8; nt++) {
            float* ac = acc[mt][nt];
            int r = i0 + wm*32 + mt*16 + (lane >> 2);
            int c = j0 + wn*64 + nt*8 + 2*(lane & 3);
            size_t base = ((size_t)h*LREF + r)*LREF + c;
            atomicAdd(&g_attn[base],            ac[0]*SC);
            atomicAdd(&g_attn[base + 1],        ac[1]*SC);
            atomicAdd(&g_attn[base + 8*LREF],   ac[2]*SC);
            atomicAdd(&g_attn[base + 8*LREF+1], ac[3]*SC);
        }
}

// -------- softmax over j per (h,i): fp32 in, bf16 out ------------------------
__global__ void __launch_bounds__(128) softmax_kernel()
{
    int i = blockIdx.x, h = blockIdx.y;
    const float* row = g_attn + ((size_t)h * LREF + i) * LREF;
    bf16* orow = g_attnb + ((size_t)h * LREF + i) * LREF;
    int tid = threadIdx.x, warp = tid >> 5, lane = tid & 31;
    __shared__ float smax[4], ssum[4];

    float a0 = row[tid], a1 = row[tid + 128], a2 = row[tid + 256];
    float m = fmaxf(a0, fmaxf(a1, a2));
#pragma unroll
    for (int o = 16; o; o >>= 1) m = fmaxf(m, __shfl_xor_sync(0xffffffffu, m, o));
    if (lane == 0) smax[warp] = m;
    __syncthreads();
    float M = fmaxf(fmaxf(smax[0], smax[1]), fmaxf(smax[2], smax[3]));

    float e0 = expf(a0 - M), e1 = expf(a1 - M), e2 = expf(a2 - M);
    float s = e0 + e1 + e2;
#pragma unroll
    for (int o = 16; o; o >>= 1) s += __shfl_xor_sync(0xffffffffu, s, o);
    if (lane == 0) ssum[warp] = s;
    __syncthreads();
    float S = ssum[0] + ssum[1] + ssum[2] + ssum[3];
    float inv = 1.f / S;
    orow[tid]       = __float2bfloat16_rn(e0 * inv);
    orow[tid + 128] = __float2bfloat16_rn(e1 * inv);
    orow[tid + 256] = __float2bfloat16_rn(e2 * inv);
}

// -------- kernel D: om[n*L+i][h*32+d] = attn_b[h] @ v  (trans-B MMA) ---------
__global__ void __launch_bounds__(256) av_kernel()
{
    extern __shared__ unsigned char sm[];
    unsigned sA = (unsigned)__cvta_generic_to_shared(sm);     // 2 x 16KB (128x64 rows 128B)
    unsigned sB = sA + 32768;                                 // 2 x 16KB (64x128 rows 256B)
    int tid = threadIdx.x, lane = tid & 31, warp = tid >> 5;
    int wm = warp & 3, wn = warp >> 2;
    int i0 = blockIdx.x * 128, col0 = blockIdx.y * 128, h = blockIdx.z;

    const bf16* ga = g_attnb + ((size_t)(h*LREF + i0))*LREF;
    const bf16* gv = g_vb + (size_t)h*LREF*KTOT + col0;

    float acc[2][8][4];
#pragma unroll
    for (int a = 0; a < 2; a++)
#pragma unroll
        for (int b = 0; b < 8; b++)
#pragma unroll
            for (int cc = 0; cc < 4; cc++) acc[a][b][cc] = 0.f;

    const int NIT = LREF/64;   // 6
    auto stage = [&](int it) {
        unsigned off = (it & 1) * 16384;
        for (int c = tid; c < 1024; c += 256) {
            int ra = c >> 3, gA = c & 7;
            cpa16(sA + off + ra*128 + ((gA ^ (ra&7))<<4), ga + (size_t)ra*LREF + it*64 + gA*8);
            int rb = c >> 4, gB = c & 15;
            cpa16(sB + off + rb*256 + ((gB ^ (rb&7))<<4), gv + (size_t)(it*64 + rb)*KTOT + gB*8);
        }
        cpa_commit();
    };
    stage(0);
    for (int it = 0; it < NIT; it++) {
        if (it + 1 < NIT) { stage(it + 1); cpa_wait<1>(); }
        else cpa_wait<0>();
        __syncthreads();
        unsigned off = (it & 1) * 16384;
#pragma unroll
        for (int kk = 0; kk < 4; kk++)
            wstep_t<2,8>(acc, sA + off, sB + off, wm*32, wn*64, kk*16, lane);
        __syncthreads();
    }

#pragma unroll
    for (int mt = 0; mt < 2; mt++)
#pragma unroll
        for (int nt = 0; nt < 8; nt++) {
            float* ac = acc[mt][nt];
            int c = col0 + wn*64 + nt*8 + 2*(lane & 3);
            int n = c >> 5, d = c & 31;
#pragma unroll
            for (int half = 0; half < 2; half++) {
                int i = i0 + wm*32 + mt*16 + (lane >> 2) + half*8;
                *(bf162*)&g_omb[((size_t)n*LREF + i)*DPC + h*DHD + d] =
                    __floats2bfloat162_rn(ac[half*2+0], ac[half*2+1]);
            }
        }
}

// -------- kernel E: y = (gate .* om) @ Wo^T + bo, write transposed -----------
__global__ void __launch_bounds__(256) out_kernel(
    const float* __restrict__ Wo, const float* __restrict__ bo, float* __restrict__ outp)
{
    extern __shared__ unsigned char sm[];
    unsigned sXa = (unsigned)__cvta_generic_to_shared(sm);   // 2 chunks x 32KB
    unsigned sWa = sXa + 65536;                              // 16KB
    int tid = threadIdx.x, lane = tid & 31, warp = tid >> 5;
    int wm = warp >> 1, wn = warp & 1;
    int row0 = blockIdx.x * 256;

    {
        int r = tid;
        size_t grow = (size_t)(row0 + r) * DPC;
#pragma unroll
        for (int g = 0; g < 16; g++) {
            uint4 gt = *(const uint4*)&g_gateb[grow + g*8];
            uint4 ot = *(const uint4*)&g_omb[grow + g*8];
            uint4 o;
            ((bf162*)&o)[0] = __hmul2(((bf162*)&gt)[0], ((bf162*)&ot)[0]);
            ((bf162*)&o)[1] = __hmul2(((bf162*)&gt)[1], ((bf162*)&ot)[1]);
            ((bf162*)&o)[2] = __hmul2(((bf162*)&gt)[2], ((bf162*)&ot)[2]);
            ((bf162*)&o)[3] = __hmul2(((bf162*)&gt)[3], ((bf162*)&ot)[3]);
            int kc = g >> 3, gg = g & 7;
            *(uint4*)(sm + kc*32768 + r*128 + ((gg ^ (r&7))<<4)) = o;
        }
    }
    __syncthreads();

    float acc[4][8][4];
#pragma unroll
    for (int a = 0; a < 4; a++)
#pragma unroll
        for (int b = 0; b < 8; b++)
#pragma unroll
            for (int cc = 0; cc < 4; cc++) acc[a][b][cc] = 0.f;

    for (int kc = 0; kc < 2; kc++) {
        __syncthreads();
        for (int c = tid; c < 1024; c += 256) {
            int r = c >> 3, g = c & 7;
            const float* src = Wo + (size_t)r*DPC + kc*64 + g*8;
            float4 t0 = *(const float4*)src;
            float4 t1 = *(const float4*)(src + 4);
            uint4 o;
            o.x = pk2(t0.x, t0.y); o.y = pk2(t0.z, t0.w);
            o.z = pk2(t1.x, t1.y); o.w = pk2(t1.z, t1.w);
            *(uint4*)(sm + 65536 + r*128 + ((g ^ (r&7))<<4)) = o;
        }
        __syncthreads();
#pragma unroll
        for (int kk = 0; kk < 4; kk++)
            wstep<4,8>(acc, sXa + kc*32768, sWa, wm*64, wn*64, kk*16, lane);
    }

#pragma unroll
    for (int mt = 0; mt < 4; mt++)
#pragma unroll
        for (int nt = 0; nt < 8; nt++) {
            float* ac = acc[mt][nt];
            int rl = wm*64 + mt*16 + (lane >> 2);
            int c  = wn*64 + nt*8 + 2*(lane & 3);
            float b0 = bo[c], b1 = bo[c+1];
#pragma unroll
            for (int half = 0; half < 2; half++) {
                int row = row0 + rl + half*8;
                int n = row / LREF, i = row - n*LREF;
                *(float2*)&outp[((size_t)i*LREF + n)*DPC + c] =
                    make_float2(ac[half*2+0] + b0, ac[half*2+1] + b1);
            }
        }
}

extern "C" void kernel_launch(void* const* d_in, const int* in_sizes, int n_in,
                              void* d_out, int out_size)
{
    (void)in_sizes; (void)n_in; (void)out_size;
    const float* pair      = (const float*)d_in[0];
    const float* bias      = (const float*)d_in[1];
    const float* ln_pair_g = (const float*)d_in[2];
    const float* ln_pair_b = (const float*)d_in[3];
    const float* ln_bias_g = (const float*)d_in[4];
    const float* ln_bias_b = (const float*)d_in[5];
    const float* Wq = (const float*)d_in[6];
    const float* Wk = (const float*)d_in[7];
    const float* Wv = (const float*)d_in[8];
    const float* Wb = (const float*)d_in[9];
    const float* Wg = (const float*)d_in[10];
    const float* bg = (const float*)d_in[11];
    const float* Wo = (const float*)d_in[12];
    const float* bo = (const float*)d_in[13];
    float* outp = (float*)d_out;

    const int PROJ_SMEM = 81920;
    const int GEMM_SMEM = 65536;
    cudaFuncSetAttribute(proj_kernel,  cudaFuncAttributeMaxDynamicSharedMemorySize, PROJ_SMEM);
    cudaFuncSetAttribute(score_kernel, cudaFuncAttributeMaxDynamicSharedMemorySize, GEMM_SMEM);
    cudaFuncSetAttribute(av_kernel,    cudaFuncAttributeMaxDynamicSharedMemorySize, GEMM_SMEM);
    cudaFuncSetAttribute(out_kernel,   cudaFuncAttributeMaxDynamicSharedMemorySize, PROJ_SMEM);

    proj_kernel<<<LREF*LREF/256, 256, PROJ_SMEM>>>(pair, ln_pair_g, ln_pair_b, Wq, Wk, Wv, Wg, bg);
    bias_kernel<<<LREF*LREF/16, 128>>>(bias, ln_bias_g, ln_bias_b, Wb);
    score_kernel<<<dim3(3, 3, 32), 256, GEMM_SMEM>>>();
    softmax_kernel<<<dim3(LREF, HN), 128>>>();
    av_kernel<<<dim3(3, KTOT/128, HN), 256, GEMM_SMEM>>>();
    out_kernel<<<LREF*LREF/256, 256, PROJ_SMEM>>>(Wo, bo, outp);
}